// round 13
// baseline (speedup 1.0000x reference)
#include <cuda_runtime.h>
#include <cuda_fp16.h>
#include <cstdint>
#include <cstddef>

// ---------------------------------------------------------------------------
// AttentionLayer B=4,N=4096,Kn=32,F=64,H=16,D=16 (fp32 in/out)
//   KP = inp@Wk + bk [32x256], VP = inp@Wv + bv
//   K[h,k,d] = KP[2h+(k>>4), (k&15)*16+d]  (same for V)
//   s = 0.25*Qh_h.K ; w = softmax_k ; out = sum_k w*V
// Single persistent kernel. P1 via ldmatrix + mma.sync.m16n8k16 fp16,
// KP/VP fp16 double-buffered (bijective quad swizzle), Qh computed inline
// (fp16 Wq), software-pipelined with ONE barrier per round.
// ---------------------------------------------------------------------------

#define FULLMASK 0xffffffffu

constexpr int PTS     = 16384;
constexpr int GRID    = 152;
constexpr int PPB     = 108;
constexpr int THREADS = 512;

// smem offsets (floats)
constexpr int O_WKT = 0;              // Wk^T [256][68] fp32 (prologue); Wq16 overlays
constexpr int O_WVT = 17408;          // Wv^T [256][68] fp32 (prologue only)
constexpr int O_KP  = 34816;          // fp16 2 x [32][264] halfs = 8448 floats
constexpr int O_VP  = 43264;          // fp16 2 x [32][280] halfs = 8960 floats
constexpr int O_A16 = 52224;          // fp16 2 x [32][72] halfs = 2304 floats
constexpr int O_QH  = 54528;          // 2 x 256 fp32
constexpr int O_QR  = 55040;          // 2 x 64 fp32 (query rows)
constexpr int O_B   = 55168;          // bk(256) | bv(256) | bq(256)
constexpr int SMEM_FLOATS = 55936;    // 223744 B
constexpr int SMEM_BYTES  = SMEM_FLOATS * 4;

constexpr int A_TILE_BYTES = 32 * 144;   // fp16 A buffer (row stride 144 B)
constexpr int KP_STRIDE = 264;           // halfs (132 words == 4 mod 32)
constexpr int VP_STRIDE = 280;           // halfs (140 words == 12 mod 32)
constexpr int KP_BUF = 32 * KP_STRIDE;   // 8448 halfs per buffer
constexpr int VP_BUF = 32 * VP_STRIDE;   // 8960 halfs per buffer

// chunk kk halfs 0-7 at quad perm(2kk), perm(q)=q^(q>>3); halfs 8-15 at ^8.
__device__ __forceinline__ int CHSW(int kk) {
    return (((2 * kk) ^ (kk >> 2)) << 3);
}
__device__ __forceinline__ uint32_t pack_h2(float lo, float hi) {
    __half2 h = __floats2half2_rn(lo, hi);
    return *(uint32_t*)&h;
}
__device__ __forceinline__ void mma_f16(float c[4], const uint32_t a[4], const uint32_t b[2]) {
    asm volatile(
        "mma.sync.aligned.m16n8k16.row.col.f32.f16.f16.f32 "
        "{%0,%1,%2,%3}, {%4,%5,%6,%7}, {%8,%9}, {%0,%1,%2,%3};"
        : "+f"(c[0]), "+f"(c[1]), "+f"(c[2]), "+f"(c[3])
        : "r"(a[0]), "r"(a[1]), "r"(a[2]), "r"(a[3]), "r"(b[0]), "r"(b[1]));
}
__device__ __forceinline__ void ldmx4(uint32_t a[4], uint32_t addr) {
    asm volatile("ldmatrix.sync.aligned.m8n8.x4.shared.b16 {%0,%1,%2,%3}, [%4];"
                 : "=r"(a[0]), "=r"(a[1]), "=r"(a[2]), "=r"(a[3]) : "r"(addr));
}
__device__ __forceinline__ uint32_t smem_u32(const void* p) {
    uint32_t a;
    asm("{ .reg .u64 t; cvta.to.shared.u64 t, %1; cvt.u32.u64 %0, t; }" : "=r"(a) : "l"(p));
    return a;
}
__device__ __forceinline__ float2 h2f(uint32_t u) {
    return __half22float2(*(__half2*)&u);
}

// ============================== Main kernel ==================================
__global__ __launch_bounds__(THREADS, 1)
void attn_main_kernel(const float* __restrict__ inp, const float* __restrict__ query,
                      const float* __restrict__ Wq, const float* __restrict__ bq,
                      const float* __restrict__ Wk, const float* __restrict__ bk,
                      const float* __restrict__ Wv, const float* __restrict__ bv,
                      float* __restrict__ out)
{
    extern __shared__ float sm[];
    char* A16 = (char*)sm + (size_t)O_A16 * 4;
    __half* KPH  = (__half*)(sm + O_KP);
    __half* VPH  = (__half*)(sm + O_VP);
    __half* WQ16 = (__half*)(sm + O_WKT);     // overlays WKT after hoist
    const int t   = threadIdx.x;
    const int wid = t >> 5;
    const int ln  = t & 31;
    const int base0 = blockIdx.x * PPB;
    const uint32_t a16_u32 = smem_u32(A16);

    const int sk  = t >> 4;            // staging: row 0..31
    const int sc4 = (t & 15) * 4;      // staging: float col

    auto clampi = [](int v) { return v < PTS ? v : PTS - 1; };

    // ---------------- prologue ----------------
    {
        const int p0 = clampi(base0), p1 = clampi(base0 + 1);
        float4 xv0 = __ldg((const float4*)(inp + (size_t)p0 * 2048 + sk * 64 + sc4));
        float4 xv1 = __ldg((const float4*)(inp + (size_t)p1 * 2048 + sk * 64 + sc4));
        float4 q40, q41;
        if (t < 16) {
            q40 = __ldg((const float4*)(query + (size_t)p0 * 64 + t * 4));
            q41 = __ldg((const float4*)(query + (size_t)p1 * 64 + t * 4));
        }
        for (int i = t; i < 4096; i += THREADS) {   // Wk^T / Wv^T fp32 staging
            int f = i >> 6, n0 = (i & 63) * 4;
            float4 a = __ldg((const float4*)Wk + i);
            sm[O_WKT + (n0 + 0) * 68 + f] = a.x;
            sm[O_WKT + (n0 + 1) * 68 + f] = a.y;
            sm[O_WKT + (n0 + 2) * 68 + f] = a.z;
            sm[O_WKT + (n0 + 3) * 68 + f] = a.w;
            float4 b = __ldg((const float4*)Wv + i);
            sm[O_WVT + (n0 + 0) * 68 + f] = b.x;
            sm[O_WVT + (n0 + 1) * 68 + f] = b.y;
            sm[O_WVT + (n0 + 2) * 68 + f] = b.z;
            sm[O_WVT + (n0 + 3) * 68 + f] = b.w;
        }
        if (t < 256) {
            sm[O_B + t] = bk[t];
            sm[O_B + 256 + t] = bv[t];
            sm[O_B + 512 + t] = bq[t];
        }
        *(uint2*)(A16 + 0 * A_TILE_BYTES + sk * 144 + sc4 * 2) =
            make_uint2(pack_h2(xv0.x, xv0.y), pack_h2(xv0.z, xv0.w));
        *(uint2*)(A16 + 1 * A_TILE_BYTES + sk * 144 + sc4 * 2) =
            make_uint2(pack_h2(xv1.x, xv1.y), pack_h2(xv1.z, xv1.w));
        if (t < 16) {
            *(float4*)(sm + O_QR + t * 4) = q40;
            *(float4*)(sm + O_QR + 64 + t * 4) = q41;
        }
        __syncthreads();
    }

    // ---- hoist fp16 B-fragments ----
    const int proj = wid >> 3;
    const int nb_  = (wid & 7) * 32;
    const int r0 = ln >> 2;
    const int cc = (ln & 3) * 2;
    uint32_t bfr[4][4][2];
    float2   b2[4];
    {
        const float* WT = sm + (proj ? O_WVT : O_WKT);
        #pragma unroll
        for (int j = 0; j < 4; ++j) {
            const int n = nb_ + j * 8 + r0;
            #pragma unroll
            for (int s = 0; s < 4; ++s) {
                const int kb = s * 16 + cc;
                bfr[j][s][0] = pack_h2(WT[n * 68 + kb],     WT[n * 68 + kb + 1]);
                bfr[j][s][1] = pack_h2(WT[n * 68 + kb + 8], WT[n * 68 + kb + 9]);
            }
            const int col = nb_ + j * 8 + cc;
            b2[j] = make_float2(sm[O_B + proj * 256 + col],
                                sm[O_B + proj * 256 + col + 1]);
        }
    }
    __syncthreads();            // all hoist reads done before WQ16 overlay

    // ---- overlay Wq as fp16 [256 rows][66 halfs] on the WKT region ----
    for (int i = t; i < 4096; i += THREADS) {
        int f = i >> 6, c0 = (i & 63) * 4;
        float4 a = __ldg((const float4*)Wq + i);
        WQ16[(c0 + 0) * 66 + f] = __float2half_rn(a.x);
        WQ16[(c0 + 1) * 66 + f] = __float2half_rn(a.y);
        WQ16[(c0 + 2) * 66 + f] = __float2half_rn(a.z);
        WQ16[(c0 + 3) * 66 + f] = __float2half_rn(a.w);
    }
    __syncthreads();

    const uint32_t lm_base = a16_u32 + (uint32_t)(ln & 15) * 144 + (uint32_t)((ln >> 4) * 8) * 2;

    // ---- P1: project A16[bi] -> KP/VP buffer bi ----
    auto do_p1 = [&](int bi) {
        float c[2][4][4];
        #pragma unroll
        for (int mi = 0; mi < 2; ++mi)
            #pragma unroll
            for (int j = 0; j < 4; ++j)
                #pragma unroll
                for (int q = 0; q < 4; ++q) c[mi][j][q] = 0.f;
        const uint32_t ab = lm_base + (uint32_t)bi * A_TILE_BYTES;
        #pragma unroll
        for (int s = 0; s < 4; ++s) {
            uint32_t a0[4], a1[4];
            ldmx4(a0, ab + s * 32);
            ldmx4(a1, ab + 2304 + s * 32);
            #pragma unroll
            for (int j = 0; j < 4; ++j) {
                mma_f16(c[0][j], a0, bfr[j][s]);
                mma_f16(c[1][j], a1, bfr[j][s]);
            }
        }
        __half* OH = (proj ? (VPH + bi * VP_BUF) : (KPH + bi * KP_BUF));
        const int OS = proj ? VP_STRIDE : KP_STRIDE;
        #pragma unroll
        for (int mi = 0; mi < 2; ++mi) {
            const int row = mi * 16 + r0;
            #pragma unroll
            for (int j = 0; j < 4; ++j) {
                const int off = (CHSW((nb_ >> 4) + (j >> 1)) ^ ((j & 1) << 3)) + cc;
                const float2 bb = b2[j];
                *(__half2*)(OH + row * OS + off) =
                    __floats2half2_rn(c[mi][j][0] + bb.x, c[mi][j][1] + bb.y);
                *(__half2*)(OH + (row + 8) * OS + off) =
                    __floats2half2_rn(c[mi][j][2] + bb.x, c[mi][j][3] + bb.y);
            }
        }
    };

    // ---- Qh: QH[qb] = bq + QR[qb] . Wq16 ----
    auto do_qh = [&](int qb) {
        if (t < 256) {
            const float* qr = sm + O_QR + qb * 64;
            const __half* wr = WQ16 + t * 66;
            float acc = sm[O_B + 512 + t];
            #pragma unroll
            for (int f2 = 0; f2 < 32; ++f2) {
                float2 wv = h2f(*(const uint32_t*)(wr + 2 * f2));
                acc = fmaf(qr[2 * f2], wv.x, fmaf(qr[2 * f2 + 1], wv.y, acc));
            }
            sm[O_QH + qb * 256 + t] = acc;
        }
    };

    // prologue tail: Qh(0), P1(0)
    do_qh(0);
    do_p1(0);
    __syncthreads();

    // ---------------- main loop: ONE barrier per round ----------------
    for (int r = 0; r < PPB; ++r) {
        const int b = r & 1;
        const int pt = clampi(base0 + r);
        const int pn2 = clampi(base0 + r + 2);

        // prefetch round r+2 inputs
        float4 xv = __ldg((const float4*)(inp + (size_t)pn2 * 2048 + sk * 64 + sc4));
        float4 q4;
        if (t < 16) q4 = __ldg((const float4*)(query + (size_t)pn2 * 64 + t * 4));

        // P1 for round r+1 (writes buffer b^1; readers use buffer b)
        if (r + 1 < PPB) do_p1(b ^ 1);

        // stage round r+2 into A16[b], QR[b]
        *(uint2*)(A16 + b * A_TILE_BYTES + sk * 144 + sc4 * 2) =
            make_uint2(pack_h2(xv.x, xv.y), pack_h2(xv.z, xv.w));
        if (t < 16)
            *(float4*)(sm + O_QR + b * 64 + t * 4) = q4;

        // ---- P2: scores + softmax for round r (warp = head h, lane = k) ----
        float w;
        const int h = wid;
        {
            const int nb = 2 * h + (ln >> 4), kk = ln & 15;
            const __half* rowp = KPH + b * KP_BUF + nb * KP_STRIDE;
            const int ho = CHSW(kk);
            uint4 u0 = *(const uint4*)(rowp + ho);
            uint4 u1 = *(const uint4*)(rowp + (ho ^ 8));
            const float* qP = sm + O_QH + b * 256 + h * 16;
            float4 qa = *(const float4*)(qP);
            float4 qb_ = *(const float4*)(qP + 4);
            float4 qc = *(const float4*)(qP + 8);
            float4 qd = *(const float4*)(qP + 12);
            float2 f0 = h2f(u0.x), f1 = h2f(u0.y), f2 = h2f(u0.z), f3 = h2f(u0.w);
            float2 f4 = h2f(u1.x), f5 = h2f(u1.y), f6 = h2f(u1.z), f7 = h2f(u1.w);
            float s = 0.f;
            s = fmaf(qa.x, f0.x, fmaf(qa.y, f0.y, fmaf(qa.z, f1.x, fmaf(qa.w, f1.y, s))));
            s = fmaf(qb_.x, f2.x, fmaf(qb_.y, f2.y, fmaf(qb_.z, f3.x, fmaf(qb_.w, f3.y, s))));
            s = fmaf(qc.x, f4.x, fmaf(qc.y, f4.y, fmaf(qc.z, f5.x, fmaf(qc.w, f5.y, s))));
            s = fmaf(qd.x, f6.x, fmaf(qd.y, f6.y, fmaf(qd.z, f7.x, fmaf(qd.w, f7.y, s))));
            s *= 0.25f;
            float m = s;
            #pragma unroll
            for (int off = 16; off; off >>= 1)
                m = fmaxf(m, __shfl_xor_sync(FULLMASK, m, off));
            float e = __expf(s - m);
            float ssum = e;
            #pragma unroll
            for (int off = 16; off; off >>= 1)
                ssum += __shfl_xor_sync(FULLMASK, ssum, off);
            w = e * __frcp_rn(ssum);
        }

        // ---- P3: output for round r ----
        {
            const int half = ln >> 4, d = ln & 15;
            const __half* vr = VPH + b * VP_BUF + (2 * h + half) * VP_STRIDE;
            const int dsel = (d >> 3) << 3, dw = d & 7;
            float acc = 0.f;
            #pragma unroll
            for (int j = 0; j < 16; ++j) {
                const float wj = __shfl_sync(FULLMASK, w, half * 16 + j);
                acc = fmaf(wj, __half2float(vr[(CHSW(j) ^ dsel) + dw]), acc);
            }
            acc += __shfl_xor_sync(FULLMASK, acc, 16);
            if (half == 0)
                out[(size_t)pt * 256 + h * 16 + d] = acc;
        }

        // ---- Qh for round r+1 (reads QR[b^1] staged in round r-1) ----
        if (r + 1 < PPB) do_qh(b ^ 1);

        __syncthreads();   // the single per-round barrier
    }
}

// ================================ launch =====================================
extern "C" void kernel_launch(void* const* d_in, const int* in_sizes, int n_in,
                              void* d_out, int out_size) {
    const float* inp   = (const float*)d_in[0];
    const float* query = (const float*)d_in[1];
    const float* Wq    = (const float*)d_in[2];
    const float* bq    = (const float*)d_in[3];
    const float* Wk    = (const float*)d_in[4];
    const float* bk    = (const float*)d_in[5];
    const float* Wv    = (const float*)d_in[6];
    const float* bv    = (const float*)d_in[7];
    float* out = (float*)d_out;

    cudaFuncSetAttribute(attn_main_kernel,
                         cudaFuncAttributeMaxDynamicSharedMemorySize, SMEM_BYTES);
    attn_main_kernel<<<GRID, THREADS, SMEM_BYTES>>>(inp, query, Wq, bq, Wk, bk, Wv, bv, out);
}

// round 14
// speedup vs baseline: 1.0752x; 1.0752x over previous
#include <cuda_runtime.h>
#include <cuda_fp16.h>
#include <cstdint>
#include <cstddef>

// ---------------------------------------------------------------------------
// AttentionLayer B=4,N=4096,Kn=32,F=64,H=16,D=16 (fp32 in/out)
//   KP = inp@Wk + bk [32x256], VP = inp@Wv + bv
//   K[h,k,d] = KP[2h+(k>>4), (k&15)*16+d]  (same for V)
//   s = 0.25*Qh_h.K ; w = softmax_k ; out = sum_k w*V
// P1 via ldmatrix + mma.sync.m16n8k16 fp16, KP/VP fp16 (bijective quad
// swizzle). TWO points per round for ILP; B-fragments hoisted from global.
// Qh = query@Wq + bq in fp32 (kernel 0).
// ---------------------------------------------------------------------------

#define FULLMASK 0xffffffffu

constexpr int PTS     = 16384;
constexpr int GRID    = 152;
constexpr int PPB     = 108;
constexpr int ROUNDS  = 54;           // 2 points per round
constexpr int THREADS = 512;

__device__ float g_Qh[(size_t)PTS * 256];

// smem offsets (floats)
constexpr int O_KP  = 0;              // fp16 2 pts x [32][264] halfs = 8448 floats
constexpr int O_VP  = 8448;           // fp16 2 pts x [32][280] halfs = 8960 floats
constexpr int O_A16 = 17408;          // fp16 2 buf x 2 pts x [32][72] halfs = 4608 floats
constexpr int O_QH  = 22016;          // 2 buf x 2 pts x 256 fp32 = 1024
constexpr int SMEM_FLOATS = 23040;    // 92160 B
constexpr int SMEM_BYTES  = SMEM_FLOATS * 4;

constexpr int A_PT_BYTES  = 32 * 144;     // 4608 B per point tile
constexpr int A_BUF_BYTES = 2 * A_PT_BYTES;
constexpr int KP_STRIDE = 264;            // halfs (132 words == 4 mod 32)
constexpr int VP_STRIDE = 280;            // halfs (140 words == 12 mod 32)
constexpr int KP_BUF = 32 * KP_STRIDE;    // per point
constexpr int VP_BUF = 32 * VP_STRIDE;

// chunk kk halfs 0-7 at quad perm(2kk), perm(q)=q^(q>>3); halfs 8-15 at ^8.
__device__ __forceinline__ int CHSW(int kk) {
    return (((2 * kk) ^ (kk >> 2)) << 3);
}
__device__ __forceinline__ uint32_t pack_h2(float lo, float hi) {
    __half2 h = __floats2half2_rn(lo, hi);
    return *(uint32_t*)&h;
}
__device__ __forceinline__ void mma_f16(float c[4], const uint32_t a[4], const uint32_t b[2]) {
    asm volatile(
        "mma.sync.aligned.m16n8k16.row.col.f32.f16.f16.f32 "
        "{%0,%1,%2,%3}, {%4,%5,%6,%7}, {%8,%9}, {%0,%1,%2,%3};"
        : "+f"(c[0]), "+f"(c[1]), "+f"(c[2]), "+f"(c[3])
        : "r"(a[0]), "r"(a[1]), "r"(a[2]), "r"(a[3]), "r"(b[0]), "r"(b[1]));
}
__device__ __forceinline__ void ldmx4(uint32_t a[4], uint32_t addr) {
    asm volatile("ldmatrix.sync.aligned.m8n8.x4.shared.b16 {%0,%1,%2,%3}, [%4];"
                 : "=r"(a[0]), "=r"(a[1]), "=r"(a[2]), "=r"(a[3]) : "r"(addr));
}
__device__ __forceinline__ uint32_t smem_u32(const void* p) {
    uint32_t a;
    asm("{ .reg .u64 t; cvta.to.shared.u64 t, %1; cvt.u32.u64 %0, t; }" : "=r"(a) : "l"(p));
    return a;
}
__device__ __forceinline__ float2 h2f(uint32_t u) {
    return __half22float2(*(__half2*)&u);
}

// ===================== Kernel 0: Qh = query @ Wq + bq (fp32) ================
constexpr int K0_BLK  = 64;
constexpr int K0_SMEM = (64 * 256 + K0_BLK * 64) * 4;   // 80 KB -> 2 CTA/SM

__global__ __launch_bounds__(256, 2)
void qproj_kernel(const float* __restrict__ query, const float* __restrict__ Wq,
                  const float* __restrict__ bq)
{
    extern __shared__ float sm[];
    float* wq = sm;
    float* q  = sm + 64 * 256;
    const int t = threadIdx.x;

    for (int i = t; i < 4096; i += 256)
        ((float4*)wq)[i] = __ldg((const float4*)Wq + i);
    const float4* qsrc = (const float4*)(query + (size_t)blockIdx.x * K0_BLK * 64);
    for (int i = t; i < K0_BLK * 16; i += 256)
        ((float4*)q)[i] = __ldg(qsrc + i);
    __syncthreads();

    const int c = t;
    const float bqc = bq[c];
    for (int p0 = 0; p0 < K0_BLK; p0 += 4) {
        float a0 = bqc, a1 = bqc, a2 = bqc, a3 = bqc;
        #pragma unroll
        for (int f4 = 0; f4 < 16; ++f4) {
            float4 q0 = *(const float4*)(q + (p0 + 0) * 64 + f4 * 4);
            float4 q1 = *(const float4*)(q + (p0 + 1) * 64 + f4 * 4);
            float4 q2 = *(const float4*)(q + (p0 + 2) * 64 + f4 * 4);
            float4 q3 = *(const float4*)(q + (p0 + 3) * 64 + f4 * 4);
            float w0 = wq[(f4 * 4 + 0) * 256 + c];
            float w1 = wq[(f4 * 4 + 1) * 256 + c];
            float w2 = wq[(f4 * 4 + 2) * 256 + c];
            float w3 = wq[(f4 * 4 + 3) * 256 + c];
            a0 = fmaf(q0.x, w0, fmaf(q0.y, w1, fmaf(q0.z, w2, fmaf(q0.w, w3, a0))));
            a1 = fmaf(q1.x, w0, fmaf(q1.y, w1, fmaf(q1.z, w2, fmaf(q1.w, w3, a1))));
            a2 = fmaf(q2.x, w0, fmaf(q2.y, w1, fmaf(q2.z, w2, fmaf(q2.w, w3, a2))));
            a3 = fmaf(q3.x, w0, fmaf(q3.y, w1, fmaf(q3.z, w2, fmaf(q3.w, w3, a3))));
        }
        size_t o = ((size_t)blockIdx.x * K0_BLK + p0) * 256 + c;
        g_Qh[o] = a0; g_Qh[o + 256] = a1; g_Qh[o + 512] = a2; g_Qh[o + 768] = a3;
    }
}

// ============================== Main kernel ==================================
__global__ __launch_bounds__(THREADS, 1)
void attn_main_kernel(const float* __restrict__ inp,
                      const float* __restrict__ Wk, const float* __restrict__ bk,
                      const float* __restrict__ Wv, const float* __restrict__ bv,
                      float* __restrict__ out)
{
    extern __shared__ float sm[];
    char* A16 = (char*)sm + (size_t)O_A16 * 4;
    __half* KPH = (__half*)(sm + O_KP);
    __half* VPH = (__half*)(sm + O_VP);
    const int t   = threadIdx.x;
    const int wid = t >> 5;
    const int ln  = t & 31;
    const int base0 = blockIdx.x * PPB;
    const uint32_t a16_u32 = smem_u32(A16);

    const int sk  = t >> 4;            // staging row 0..31
    const int sc4 = (t & 15) * 4;      // staging float col

    auto clampi = [](int v) { return v < PTS ? v : PTS - 1; };

    // ---- hoist fp16 B-fragments straight from global (one-time, L2-hot) ----
    const int proj = wid >> 3;
    const int nb_  = (wid & 7) * 32;
    const int r0 = ln >> 2;
    const int cc = (ln & 3) * 2;
    const float* Wsrc = proj ? Wv : Wk;
    const float* bsrc = proj ? bv : bk;
    uint32_t bfr[4][4][2];
    float2   b2[4];
    #pragma unroll
    for (int j = 0; j < 4; ++j) {
        const int n = nb_ + j * 8 + r0;
        #pragma unroll
        for (int s = 0; s < 4; ++s) {
            const int f = s * 16 + cc;
            bfr[j][s][0] = pack_h2(__ldg(Wsrc + (f + 0) * 256 + n),
                                   __ldg(Wsrc + (f + 1) * 256 + n));
            bfr[j][s][1] = pack_h2(__ldg(Wsrc + (f + 8) * 256 + n),
                                   __ldg(Wsrc + (f + 9) * 256 + n));
        }
        const int col = nb_ + j * 8 + cc;
        b2[j] = make_float2(__ldg(bsrc + col), __ldg(bsrc + col + 1));
    }

    // ---- prologue: stage round-0 tiles (2 points) + QH ----
    {
        const int p0 = clampi(base0), p1 = clampi(base0 + 1);
        float4 x0 = __ldg((const float4*)(inp + (size_t)p0 * 2048 + sk * 64 + sc4));
        float4 x1 = __ldg((const float4*)(inp + (size_t)p1 * 2048 + sk * 64 + sc4));
        *(uint2*)(A16 + 0 * A_PT_BYTES + sk * 144 + sc4 * 2) =
            make_uint2(pack_h2(x0.x, x0.y), pack_h2(x0.z, x0.w));
        *(uint2*)(A16 + 1 * A_PT_BYTES + sk * 144 + sc4 * 2) =
            make_uint2(pack_h2(x1.x, x1.y), pack_h2(x1.z, x1.w));
        if (t < 64) {
            float4 qa = __ldg((const float4*)(g_Qh + (size_t)p0 * 256 + t * 4));
            float4 qb = __ldg((const float4*)(g_Qh + (size_t)p1 * 256 + t * 4));
            *(float4*)(sm + O_QH + t * 4) = qa;
            *(float4*)(sm + O_QH + 256 + t * 4) = qb;
        }
        __syncthreads();
    }

    const uint32_t lm_base = a16_u32 + (uint32_t)(ln & 15) * 144 + (uint32_t)((ln >> 4) * 8) * 2;

    // P1 for one point: A16[buf][pi] -> KP/VP slot pi
    auto do_p1 = [&](int buf, int pi) {
        float c[2][4][4];
        #pragma unroll
        for (int mi = 0; mi < 2; ++mi)
            #pragma unroll
            for (int j = 0; j < 4; ++j)
                #pragma unroll
                for (int q = 0; q < 4; ++q) c[mi][j][q] = 0.f;
        const uint32_t ab = lm_base + (uint32_t)(buf * A_BUF_BYTES + pi * A_PT_BYTES);
        #pragma unroll
        for (int s = 0; s < 4; ++s) {
            uint32_t a0[4], a1[4];
            ldmx4(a0, ab + s * 32);
            ldmx4(a1, ab + 2304 + s * 32);
            #pragma unroll
            for (int j = 0; j < 4; ++j) {
                mma_f16(c[0][j], a0, bfr[j][s]);
                mma_f16(c[1][j], a1, bfr[j][s]);
            }
        }
        __half* OH = (proj ? (VPH + pi * VP_BUF) : (KPH + pi * KP_BUF));
        const int OS = proj ? VP_STRIDE : KP_STRIDE;
        #pragma unroll
        for (int mi = 0; mi < 2; ++mi) {
            const int row = mi * 16 + r0;
            #pragma unroll
            for (int j = 0; j < 4; ++j) {
                const int off = (CHSW((nb_ >> 4) + (j >> 1)) ^ ((j & 1) << 3)) + cc;
                const float2 bb = b2[j];
                *(__half2*)(OH + row * OS + off) =
                    __floats2half2_rn(c[mi][j][0] + bb.x, c[mi][j][1] + bb.y);
                *(__half2*)(OH + (row + 8) * OS + off) =
                    __floats2half2_rn(c[mi][j][2] + bb.x, c[mi][j][3] + bb.y);
            }
        }
    };

    for (int r = 0; r < ROUNDS; ++r) {
        const int b = r & 1;
        const int pt0 = clampi(base0 + 2 * r);
        const int pt1 = clampi(base0 + 2 * r + 1);
        const int n0  = clampi(base0 + 2 * r + 2);
        const int n1  = clampi(base0 + 2 * r + 3);

        // prefetch next round's inputs (consumed mid-round)
        float4 x0 = __ldg((const float4*)(inp + (size_t)n0 * 2048 + sk * 64 + sc4));
        float4 x1 = __ldg((const float4*)(inp + (size_t)n1 * 2048 + sk * 64 + sc4));
        float4 qa, qb;
        if (t < 64) {
            qa = __ldg((const float4*)(g_Qh + (size_t)n0 * 256 + t * 4));
            qb = __ldg((const float4*)(g_Qh + (size_t)n1 * 256 + t * 4));
        }

        __syncthreads();     // B1: prev round's KP/VP readers done; A16[b^1] free

        // ---- P1 x2: independent chains for ILP ----
        do_p1(b, 0);
        do_p1(b, 1);

        // stage next round into A16[b^1], QH[b^1]
        *(uint2*)(A16 + (b ^ 1) * A_BUF_BYTES + 0 * A_PT_BYTES + sk * 144 + sc4 * 2) =
            make_uint2(pack_h2(x0.x, x0.y), pack_h2(x0.z, x0.w));
        *(uint2*)(A16 + (b ^ 1) * A_BUF_BYTES + 1 * A_PT_BYTES + sk * 144 + sc4 * 2) =
            make_uint2(pack_h2(x1.x, x1.y), pack_h2(x1.z, x1.w));
        if (t < 64) {
            *(float4*)(sm + O_QH + (b ^ 1) * 512 + t * 4) = qa;
            *(float4*)(sm + O_QH + (b ^ 1) * 512 + 256 + t * 4) = qb;
        }

        __syncthreads();     // B2: KP/VP visible

        // ---- P2+P3 for both points (warp = head h) ----
        const int h = wid;
        #pragma unroll
        for (int p = 0; p < 2; ++p) {
            const int pt = p ? pt1 : pt0;
            float w;
            {
                const int nb = 2 * h + (ln >> 4), kk = ln & 15;
                const __half* rowp = KPH + p * KP_BUF + nb * KP_STRIDE;
                const int ho = CHSW(kk);
                uint4 u0 = *(const uint4*)(rowp + ho);
                uint4 u1 = *(const uint4*)(rowp + (ho ^ 8));
                const float* qP = sm + O_QH + b * 512 + p * 256 + h * 16;
                float4 qv0 = *(const float4*)(qP);
                float4 qv1 = *(const float4*)(qP + 4);
                float4 qv2 = *(const float4*)(qP + 8);
                float4 qv3 = *(const float4*)(qP + 12);
                float2 f0 = h2f(u0.x), f1 = h2f(u0.y), f2 = h2f(u0.z), f3 = h2f(u0.w);
                float2 f4 = h2f(u1.x), f5 = h2f(u1.y), f6 = h2f(u1.z), f7 = h2f(u1.w);
                float s = 0.f;
                s = fmaf(qv0.x, f0.x, fmaf(qv0.y, f0.y, fmaf(qv0.z, f1.x, fmaf(qv0.w, f1.y, s))));
                s = fmaf(qv1.x, f2.x, fmaf(qv1.y, f2.y, fmaf(qv1.z, f3.x, fmaf(qv1.w, f3.y, s))));
                s = fmaf(qv2.x, f4.x, fmaf(qv2.y, f4.y, fmaf(qv2.z, f5.x, fmaf(qv2.w, f5.y, s))));
                s = fmaf(qv3.x, f6.x, fmaf(qv3.y, f6.y, fmaf(qv3.z, f7.x, fmaf(qv3.w, f7.y, s))));
                s *= 0.25f;
                float m = s;
                #pragma unroll
                for (int off = 16; off; off >>= 1)
                    m = fmaxf(m, __shfl_xor_sync(FULLMASK, m, off));
                float e = __expf(s - m);
                float ssum = e;
                #pragma unroll
                for (int off = 16; off; off >>= 1)
                    ssum += __shfl_xor_sync(FULLMASK, ssum, off);
                w = e * __frcp_rn(ssum);
            }
            {
                const int half = ln >> 4, d = ln & 15;
                const __half* vr = VPH + p * VP_BUF + (2 * h + half) * VP_STRIDE;
                const int dsel = (d >> 3) << 3, dw = d & 7;
                float acc = 0.f;
                #pragma unroll
                for (int j = 0; j < 16; ++j) {
                    const float wj = __shfl_sync(FULLMASK, w, half * 16 + j);
                    acc = fmaf(wj, __half2float(vr[(CHSW(j) ^ dsel) + dw]), acc);
                }
                acc += __shfl_xor_sync(FULLMASK, acc, 16);
                if (half == 0)
                    out[(size_t)pt * 256 + h * 16 + d] = acc;
            }
        }
        // next round's B1 gates KP/VP/A16 reuse
    }
}

// ================================ launch =====================================
extern "C" void kernel_launch(void* const* d_in, const int* in_sizes, int n_in,
                              void* d_out, int out_size) {
    const float* inp   = (const float*)d_in[0];
    const float* query = (const float*)d_in[1];
    const float* Wq    = (const float*)d_in[2];
    const float* bq    = (const float*)d_in[3];
    const float* Wk    = (const float*)d_in[4];
    const float* bk    = (const float*)d_in[5];
    const float* Wv    = (const float*)d_in[6];
    const float* bv    = (const float*)d_in[7];
    float* out = (float*)d_out;

    cudaFuncSetAttribute(qproj_kernel,
                         cudaFuncAttributeMaxDynamicSharedMemorySize, K0_SMEM);
    cudaFuncSetAttribute(attn_main_kernel,
                         cudaFuncAttributeMaxDynamicSharedMemorySize, SMEM_BYTES);

    qproj_kernel<<<PTS / K0_BLK, 256, K0_SMEM>>>(query, Wq, bq);
    attn_main_kernel<<<GRID, THREADS, SMEM_BYTES>>>(inp, Wk, bk, Wv, bv, out);
}

// round 15
// speedup vs baseline: 1.3817x; 1.2851x over previous
#include <cuda_runtime.h>
#include <cuda_fp16.h>
#include <cstdint>
#include <cstddef>

// ---------------------------------------------------------------------------
// AttentionLayer B=4,N=4096,Kn=32,F=64,H=16,D=16 (fp32 in/out)
//   KP = inp@Wk + bk [32x256], VP = inp@Wv + bv
//   K[h,k,d] = KP[2h+(k>>4), (k&15)*16+d]  (same for V)
//   s = 0.25*Qh_h.K ; w = softmax_k ; out = sum_k w*V
// ONE kernel. Prologue computes the block's own 108 Qh rows via the same
// ldmatrix+mma m16n8k16 fp16 pipeline into resident smem (fp16). Main loop =
// round-12 structure: P1 MMA -> fp16 KP/VP (bijective quad swizzle) -> fused
// softmax/output. No global Qh round-trip, no second kernel.
// ---------------------------------------------------------------------------

#define FULLMASK 0xffffffffu

constexpr int PTS     = 16384;
constexpr int GRID    = 152;
constexpr int PPB     = 108;
constexpr int THREADS = 512;

// smem offsets (floats)
constexpr int O_KP   = 0;               // fp16 [32][264] halfs = 4224 fl
constexpr int O_VP   = 4224;            // fp16 [32][280] halfs = 4480 fl
constexpr int O_A16  = 8704;            // fp16 2 x [32][72] halfs = 2304 fl
constexpr int O_QHS  = 11008;           // fp16 [128][264] halfs = 16896 fl
constexpr int SMEM_FLOATS = 27904;      // 111616 B
constexpr int SMEM_BYTES  = SMEM_FLOATS * 4;

constexpr int A_TILE_BYTES = 32 * 144;  // per A buffer
constexpr int KP_STRIDE = 264;          // halfs (132 words == 4 mod 32)
constexpr int VP_STRIDE = 280;          // halfs (140 words == 12 mod 32)
constexpr int QH_STRIDE = 264;          // halfs

// chunk kk halfs 0-7 at quad perm(2kk), perm(q)=q^(q>>3); halfs 8-15 at ^8.
__device__ __forceinline__ int CHSW(int kk) {
    return (((2 * kk) ^ (kk >> 2)) << 3);
}
__device__ __forceinline__ uint32_t pack_h2(float lo, float hi) {
    __half2 h = __floats2half2_rn(lo, hi);
    return *(uint32_t*)&h;
}
__device__ __forceinline__ void mma_f16(float c[4], const uint32_t a[4], const uint32_t b[2]) {
    asm volatile(
        "mma.sync.aligned.m16n8k16.row.col.f32.f16.f16.f32 "
        "{%0,%1,%2,%3}, {%4,%5,%6,%7}, {%8,%9}, {%0,%1,%2,%3};"
        : "+f"(c[0]), "+f"(c[1]), "+f"(c[2]), "+f"(c[3])
        : "r"(a[0]), "r"(a[1]), "r"(a[2]), "r"(a[3]), "r"(b[0]), "r"(b[1]));
}
__device__ __forceinline__ void ldmx4(uint32_t a[4], uint32_t addr) {
    asm volatile("ldmatrix.sync.aligned.m8n8.x4.shared.b16 {%0,%1,%2,%3}, [%4];"
                 : "=r"(a[0]), "=r"(a[1]), "=r"(a[2]), "=r"(a[3]) : "r"(addr));
}
__device__ __forceinline__ uint32_t smem_u32(const void* p) {
    uint32_t a;
    asm("{ .reg .u64 t; cvta.to.shared.u64 t, %1; cvt.u32.u64 %0, t; }" : "=r"(a) : "l"(p));
    return a;
}
__device__ __forceinline__ float2 h2f(uint32_t u) {
    return __half22float2(*(__half2*)&u);
}

// ============================== Main kernel ==================================
__global__ __launch_bounds__(THREADS, 1)
void attn_main_kernel(const float* __restrict__ inp, const float* __restrict__ query,
                      const float* __restrict__ Wq, const float* __restrict__ bq,
                      const float* __restrict__ Wk, const float* __restrict__ bk,
                      const float* __restrict__ Wv, const float* __restrict__ bv,
                      float* __restrict__ out)
{
    extern __shared__ float sm[];
    char*   A16 = (char*)sm + (size_t)O_A16 * 4;
    __half* KPH = (__half*)(sm + O_KP);
    __half* VPH = (__half*)(sm + O_VP);
    __half* QHS = (__half*)(sm + O_QHS);
    const int t   = threadIdx.x;
    const int wid = t >> 5;
    const int ln  = t & 31;
    const int base0 = blockIdx.x * PPB;
    const uint32_t a16_u32 = smem_u32(A16);
    const uint32_t qa16_u32 = smem_u32(KPH);   // prologue overlay region

    const int sk  = t >> 4;            // staging row 0..31
    const int sc4 = (t & 15) * 4;      // staging float col

    auto clampi = [](int v) { return v < PTS ? v : PTS - 1; };

    // fragment geometry (shared by prologue and main loop)
    const int nb_ = (wid & 7) * 32;
    const int r0  = ln >> 2;
    const int cc  = (ln & 3) * 2;

    // =================== PROLOGUE: Qh for this block's points ===============
    {
        // stage 128 query rows fp16 at [row][72 halfs] over the KP/VP region
        #pragma unroll
        for (int i = 0; i < 4; ++i) {
            const int idx = t + i * THREADS;           // 0..2047
            const int row = idx >> 4, c4 = (idx & 15) * 4;
            const int pr  = clampi(base0 + (row < PPB ? row : PPB - 1));
            float4 qv = __ldg((const float4*)(query + (size_t)pr * 64 + c4));
            *(uint2*)((char*)KPH + row * 144 + c4 * 2) =
                make_uint2(pack_h2(qv.x, qv.y), pack_h2(qv.z, qv.w));
        }
        // stage A16 tile for round 0
        {
            const int p0 = clampi(base0);
            float4 xv = __ldg((const float4*)(inp + (size_t)p0 * 2048 + sk * 64 + sc4));
            *(uint2*)(A16 + sk * 144 + sc4 * 2) =
                make_uint2(pack_h2(xv.x, xv.y), pack_h2(xv.z, xv.w));
        }
        // hoist Wq fragments (transient registers)
        uint32_t wqf[4][4][2];
        float2   bq2[4];
        #pragma unroll
        for (int j = 0; j < 4; ++j) {
            const int n = nb_ + j * 8 + r0;
            #pragma unroll
            for (int s = 0; s < 4; ++s) {
                const int f = s * 16 + cc;
                wqf[j][s][0] = pack_h2(__ldg(Wq + (f + 0) * 256 + n),
                                       __ldg(Wq + (f + 1) * 256 + n));
                wqf[j][s][1] = pack_h2(__ldg(Wq + (f + 8) * 256 + n),
                                       __ldg(Wq + (f + 9) * 256 + n));
            }
            const int col = nb_ + j * 8 + cc;
            bq2[j] = make_float2(__ldg(bq + col), __ldg(bq + col + 1));
        }
        __syncthreads();

        // 16 warps x 2 M-tiles: warp wid covers n-range nb_, m-tiles (wid>>3)*2+{0,1}
        const uint32_t qlm = qa16_u32 + (uint32_t)(ln & 15) * 144 + (uint32_t)((ln >> 4) * 8) * 2;
        #pragma unroll
        for (int task = 0; task < 2; ++task) {
            const int mt = (wid >> 3) * 2 + task;      // 0..3 -> rows mt*32..+31
            float c[2][4][4];
            #pragma unroll
            for (int mi = 0; mi < 2; ++mi)
                #pragma unroll
                for (int j = 0; j < 4; ++j)
                    #pragma unroll
                    for (int q = 0; q < 4; ++q) c[mi][j][q] = 0.f;
            const uint32_t ab = qlm + (uint32_t)(mt * 32 * 144);
            #pragma unroll
            for (int s = 0; s < 4; ++s) {
                uint32_t a0[4], a1[4];
                ldmx4(a0, ab + s * 32);
                ldmx4(a1, ab + 2304 + s * 32);
                #pragma unroll
                for (int j = 0; j < 4; ++j) {
                    mma_f16(c[0][j], a0, wqf[j][s]);
                    mma_f16(c[1][j], a1, wqf[j][s]);
                }
            }
            #pragma unroll
            for (int mi = 0; mi < 2; ++mi) {
                const int row = mt * 32 + mi * 16 + r0;
                #pragma unroll
                for (int j = 0; j < 4; ++j) {
                    const int col = nb_ + j * 8 + cc;
                    const float2 bb = bq2[j];
                    *(__half2*)(QHS + row * QH_STRIDE + col) =
                        __floats2half2_rn(c[mi][j][0] + bb.x, c[mi][j][1] + bb.y);
                    *(__half2*)(QHS + (row + 8) * QH_STRIDE + col) =
                        __floats2half2_rn(c[mi][j][2] + bb.x, c[mi][j][3] + bb.y);
                }
            }
        }
    }

    // ---- hoist Wk/Wv fragments + biases from global (persistent) ----
    const int proj = wid >> 3;
    const float* Wsrc = proj ? Wv : Wk;
    const float* bsrc = proj ? bv : bk;
    uint32_t bfr[4][4][2];
    float2   b2[4];
    #pragma unroll
    for (int j = 0; j < 4; ++j) {
        const int n = nb_ + j * 8 + r0;
        #pragma unroll
        for (int s = 0; s < 4; ++s) {
            const int f = s * 16 + cc;
            bfr[j][s][0] = pack_h2(__ldg(Wsrc + (f + 0) * 256 + n),
                                   __ldg(Wsrc + (f + 1) * 256 + n));
            bfr[j][s][1] = pack_h2(__ldg(Wsrc + (f + 8) * 256 + n),
                                   __ldg(Wsrc + (f + 9) * 256 + n));
        }
        const int col = nb_ + j * 8 + cc;
        b2[j] = make_float2(__ldg(bsrc + col), __ldg(bsrc + col + 1));
    }
    __syncthreads();   // QHS complete; prologue QA16 reads done before KP writes

    const uint32_t lm_base = a16_u32 + (uint32_t)(ln & 15) * 144 + (uint32_t)((ln >> 4) * 8) * 2;

    // ========================= MAIN LOOP (round-12) =========================
    for (int r = 0; r < PPB; ++r) {
        const int buf = r & 1;
        const int pt  = clampi(base0 + r);
        const int ptn = clampi(base0 + r + 1);

        // prefetch next point's inp tile (consumed mid-round)
        float4 xv = __ldg((const float4*)(inp + (size_t)ptn * 2048 + sk * 64 + sc4));

        __syncthreads();     // B1: prev round's KP/VP readers done

        // ---- P1: KP/VP via ldmatrix + mma m16n8k16 fp16, store fp16 swizzled ----
        {
            float c[2][4][4];
            #pragma unroll
            for (int mi = 0; mi < 2; ++mi)
                #pragma unroll
                for (int j = 0; j < 4; ++j)
                    #pragma unroll
                    for (int q = 0; q < 4; ++q) c[mi][j][q] = 0.f;

            const uint32_t ab = lm_base + (uint32_t)buf * A_TILE_BYTES;
            #pragma unroll
            for (int s = 0; s < 4; ++s) {
                uint32_t a0[4], a1[4];
                ldmx4(a0, ab + s * 32);
                ldmx4(a1, ab + 2304 + s * 32);
                #pragma unroll
                for (int j = 0; j < 4; ++j) {
                    mma_f16(c[0][j], a0, bfr[j][s]);
                    mma_f16(c[1][j], a1, bfr[j][s]);
                }
            }
            __half* OH = proj ? VPH : KPH;
            const int OS = proj ? VP_STRIDE : KP_STRIDE;
            #pragma unroll
            for (int mi = 0; mi < 2; ++mi) {
                const int row = mi * 16 + r0;
                #pragma unroll
                for (int j = 0; j < 4; ++j) {
                    const int off = (CHSW((nb_ >> 4) + (j >> 1)) ^ ((j & 1) << 3)) + cc;
                    const float2 bb = b2[j];
                    *(__half2*)(OH + row * OS + off) =
                        __floats2half2_rn(c[mi][j][0] + bb.x, c[mi][j][1] + bb.y);
                    *(__half2*)(OH + (row + 8) * OS + off) =
                        __floats2half2_rn(c[mi][j][2] + bb.x, c[mi][j][3] + bb.y);
                }
            }
        }

        // stage next tile while P1 stores drain
        *(uint2*)(A16 + (buf ^ 1) * A_TILE_BYTES + sk * 144 + sc4 * 2) =
            make_uint2(pack_h2(xv.x, xv.y), pack_h2(xv.z, xv.w));

        __syncthreads();     // B2: KP/VP visible

        // ---- P2: scores + softmax (warp = head h, lane = k) ----
        float w;
        const int h = wid;
        {
            const int nb = 2 * h + (ln >> 4), kk = ln & 15;
            const __half* rowp = KPH + nb * KP_STRIDE;
            const int ho = CHSW(kk);
            uint4 u0 = *(const uint4*)(rowp + ho);
            uint4 u1 = *(const uint4*)(rowp + (ho ^ 8));
            const __half* qhp = QHS + r * QH_STRIDE + h * 16;   // broadcast reads
            uint4 q0 = *(const uint4*)(qhp);
            uint4 q1 = *(const uint4*)(qhp + 8);
            float2 f0 = h2f(u0.x), f1 = h2f(u0.y), f2 = h2f(u0.z), f3 = h2f(u0.w);
            float2 f4 = h2f(u1.x), f5 = h2f(u1.y), f6 = h2f(u1.z), f7 = h2f(u1.w);
            float2 g0 = h2f(q0.x), g1 = h2f(q0.y), g2 = h2f(q0.z), g3 = h2f(q0.w);
            float2 g4 = h2f(q1.x), g5 = h2f(q1.y), g6 = h2f(q1.z), g7 = h2f(q1.w);
            float s = 0.f;
            s = fmaf(g0.x, f0.x, fmaf(g0.y, f0.y, fmaf(g1.x, f1.x, fmaf(g1.y, f1.y, s))));
            s = fmaf(g2.x, f2.x, fmaf(g2.y, f2.y, fmaf(g3.x, f3.x, fmaf(g3.y, f3.y, s))));
            s = fmaf(g4.x, f4.x, fmaf(g4.y, f4.y, fmaf(g5.x, f5.x, fmaf(g5.y, f5.y, s))));
            s = fmaf(g6.x, f6.x, fmaf(g6.y, f6.y, fmaf(g7.x, f7.x, fmaf(g7.y, f7.y, s))));
            s *= 0.25f;
            float m = s;
            #pragma unroll
            for (int off = 16; off; off >>= 1)
                m = fmaxf(m, __shfl_xor_sync(FULLMASK, m, off));
            float e = __expf(s - m);
            float ssum = e;
            #pragma unroll
            for (int off = 16; off; off >>= 1)
                ssum += __shfl_xor_sync(FULLMASK, ssum, off);
            w = e * __frcp_rn(ssum);
        }

        // ---- P3: output ----
        {
            const int half = ln >> 4, d = ln & 15;
            const __half* vr = VPH + (2 * h + half) * VP_STRIDE;
            const int dsel = (d >> 3) << 3, dw = d & 7;
            float acc = 0.f;
            #pragma unroll
            for (int j = 0; j < 16; ++j) {
                const float wj = __shfl_sync(FULLMASK, w, half * 16 + j);
                acc = fmaf(wj, __half2float(vr[(CHSW(j) ^ dsel) + dw]), acc);
            }
            acc += __shfl_xor_sync(FULLMASK, acc, 16);
            if (half == 0)
                out[(size_t)pt * 256 + h * 16 + d] = acc;
        }
        // next round's B1 gates KP/VP/A16 reuse
    }
}

// ================================ launch =====================================
extern "C" void kernel_launch(void* const* d_in, const int* in_sizes, int n_in,
                              void* d_out, int out_size) {
    const float* inp   = (const float*)d_in[0];
    const float* query = (const float*)d_in[1];
    const float* Wq    = (const float*)d_in[2];
    const float* bq    = (const float*)d_in[3];
    const float* Wk    = (const float*)d_in[4];
    const float* bk    = (const float*)d_in[5];
    const float* Wv    = (const float*)d_in[6];
    const float* bv    = (const float*)d_in[7];
    float* out = (float*)d_out;

    cudaFuncSetAttribute(attn_main_kernel,
                         cudaFuncAttributeMaxDynamicSharedMemorySize, SMEM_BYTES);
    attn_main_kernel<<<GRID, THREADS, SMEM_BYTES>>>(inp, query, Wq, bq, Wk, bk, Wv, bv, out);
}